// round 11
// baseline (speedup 1.0000x reference)
#include <cuda_runtime.h>
#include <cstdint>
#include <math_constants.h>

#define N_NODES 100000
#define N_EDGES 800000
#define DIM 64
#define HEADS 4
#define NCHUNK 98   // ceil(N_NODES/1024)

// ---------------- scratch (static __device__, no allocations) ----------------
__device__ float g_q[N_NODES * DIM];
__device__ float g_k[N_NODES * DIM];
__device__ float g_v[N_NODES * DIM];
__device__ float g_p[N_NODES * DIM * HEADS];     // [n][h*64+j]
__device__ float g_att[N_EDGES * HEADS];         // CSR order: logits -> exp(logit-m)
__device__ float g_dinv[N_NODES * HEADS];        // 1/(denom+eps)
__device__ int   g_src[N_EDGES];
__device__ int   g_dst[N_EDGES];
__device__ int   g_csr_src[N_EDGES];
__device__ int   g_csr_dst[N_EDGES];
__device__ int   g_csr_eid[N_EDGES];
__device__ int   g_deg[N_NODES];
__device__ int   g_rowptr[N_NODES + 1];
__device__ int   g_cursor[N_NODES];
__device__ int   g_chunksum[NCHUNK];
__device__ int   g_chunkoff[NCHUNK];
__device__ unsigned g_menc[N_NODES * HEADS];
__device__ float g_denom[N_NODES * HEADS];
__device__ float g_zA[N_NODES * DIM];
__device__ float g_zB[N_NODES * DIM];
__device__ int   g_is64;

// ordered-uint encoding of float for atomicMax
__device__ __forceinline__ unsigned fenc(float f) {
    unsigned u = __float_as_uint(f);
    return (u & 0x80000000u) ? ~u : (u | 0x80000000u);
}
__device__ __forceinline__ float fdec(unsigned u) {
    unsigned b = (u & 0x80000000u) ? (u & 0x7FFFFFFFu) : ~u;
    return __uint_as_float(b);
}

// packed f32x2 helpers (FFMA2 is only reachable via PTX fma.rn.f32x2)
__device__ __forceinline__ unsigned long long pk2(float a, float b) {
    unsigned long long r;
    asm("mov.b64 %0, {%1, %2};" : "=l"(r) : "f"(a), "f"(b));
    return r;
}
__device__ __forceinline__ unsigned long long ffma2(unsigned long long a,
                                                    unsigned long long b,
                                                    unsigned long long c) {
    unsigned long long d;
    asm("fma.rn.f32x2 %0, %1, %2, %3;" : "=l"(d) : "l"(a), "l"(b), "l"(c));
    return d;
}
__device__ __forceinline__ void upk2(unsigned long long v, float& lo, float& hi) {
    asm("mov.b64 {%0, %1}, %2;" : "=f"(lo), "=f"(hi) : "l"(v));
}

// ---------------- kernels ----------------

// fused: dtype detect (thread 0 of block 0) + zero-init of deg/menc/denom
__global__ void k_init(const long long* __restrict__ ei) {
    int i = blockIdx.x * blockDim.x + threadIdx.x;
    if (i == 0) {
        int ok = 1;
        for (int j = 0; j < 64; j++) {
            long long v = ei[j];
            if (v < 0 || v >= N_NODES) ok = 0;
        }
        g_is64 = ok;
    }
    if (i < N_NODES * HEADS) { g_menc[i] = 0u; g_denom[i] = 0.0f; }
    if (i < N_NODES) g_deg[i] = 0;
}

__global__ void k_prep(const long long* __restrict__ ei) {
    int i = blockIdx.x * blockDim.x + threadIdx.x;
    if (i >= N_EDGES) return;
    int s, d;
    if (g_is64) {
        s = (int)ei[i];
        d = (int)ei[N_EDGES + i];
    } else {
        const int* e32 = (const int*)ei;
        s = e32[i];
        d = e32[N_EDGES + i];
    }
    g_src[i] = s;
    g_dst[i] = d;
    atomicAdd(&g_deg[d], 1);
}

// q/k/v projections with packed f32x2 FMA, 64 rows/block (16 rows/thread)
// to amortize the per-j weight load + pack overhead over 24 FFMA2.
// xs[dim][row] transposed staging, stride 66 (8B-aligned row-pair loads,
// broadcast within warp since all lanes share rg).
__global__ void k_qkv(const float* __restrict__ x, const float* __restrict__ Wq,
                      const float* __restrict__ Wk, const float* __restrict__ Wv) {
    __shared__ float xs[64][66];
    int n0 = blockIdx.x * 64;
    int t = threadIdx.x;
    int lim = N_NODES * 64 - n0 * 64;
    for (int kk = 0; kk < 16; kk++) {
        int L = kk * 256 + t;            // L = row*64 + dim
        if (L < lim) xs[L & 63][L >> 6] = x[n0 * 64 + L];
    }
    __syncthreads();
    int col = t & 63, rg = t >> 6;       // rg in [0,4), 16 rows each
    unsigned long long aq[8], ak[8], av[8];
#pragma unroll
    for (int rp = 0; rp < 8; rp++) { aq[rp] = 0ull; ak[rp] = 0ull; av[rp] = 0ull; }
#pragma unroll 2
    for (int j = 0; j < 64; j++) {
        float wq = Wq[j * 64 + col];
        float wk = Wk[j * 64 + col];
        float wv = Wv[j * 64 + col];
        unsigned long long wq2 = pk2(wq, wq);
        unsigned long long wk2 = pk2(wk, wk);
        unsigned long long wv2 = pk2(wv, wv);
        const unsigned long long* xr =
            (const unsigned long long*)&xs[j][rg * 16];  // even offset: j*66+rg*16
#pragma unroll
        for (int rp = 0; rp < 8; rp++) {
            unsigned long long xv2 = xr[rp];             // rows {rg*16+2rp, +1}
            aq[rp] = ffma2(xv2, wq2, aq[rp]);
            ak[rp] = ffma2(xv2, wk2, ak[rp]);
            av[rp] = ffma2(xv2, wv2, av[rp]);
        }
    }
#pragma unroll
    for (int rp = 0; rp < 8; rp++) {
        int n = n0 + rg * 16 + rp * 2;
        if (n >= N_NODES) break;         // N even; pairs stay in-bounds together
        float lo, hi;
        upk2(aq[rp], lo, hi);
        g_q[n * 64 + col] = lo; g_q[(n + 1) * 64 + col] = hi;
        upk2(ak[rp], lo, hi);
        g_k[n * 64 + col] = lo; g_k[(n + 1) * 64 + col] = hi;
        upk2(av[rp], lo, hi);
        g_v[n * 64 + col] = lo; g_v[(n + 1) * 64 + col] = hi;
    }
}

// p[n,h,j] = sum_d We[j, h*16+d] * q[n, h*16+d]   (16 nodes per block)
__global__ void k_p(const float* __restrict__ We) {
    __shared__ float qs[16][64];
    int n0 = blockIdx.x * 16, t = threadIdx.x;
    for (int k = 0; k < 4; k++) {
        int L = k * 256 + t;
        qs[L >> 6][L & 63] = g_q[n0 * 64 + L];
    }
    __syncthreads();
    int h = t >> 6, j = t & 63;
    const float4* wp = (const float4*)(We + j * 64 + h * 16);
    float4 w0 = wp[0], w1 = wp[1], w2 = wp[2], w3 = wp[3];
#pragma unroll 4
    for (int nl = 0; nl < 16; nl++) {
        const float* qr = &qs[nl][h * 16];
        float acc = w0.x * qr[0] + w0.y * qr[1] + w0.z * qr[2] + w0.w * qr[3]
                  + w1.x * qr[4] + w1.y * qr[5] + w1.z * qr[6] + w1.w * qr[7]
                  + w2.x * qr[8] + w2.y * qr[9] + w2.z * qr[10] + w2.w * qr[11]
                  + w3.x * qr[12] + w3.y * qr[13] + w3.z * qr[14] + w3.w * qr[15];
        g_p[(n0 + nl) * 256 + h * 64 + j] = acc;
    }
}

__global__ void k_chunksum() {
    __shared__ int sh[256];
    int b = blockIdx.x, t = threadIdx.x;
    int base = b * 1024;
    int sum = 0;
    for (int k = 0; k < 4; k++) {
        int i = base + k * 256 + t;
        if (i < N_NODES) sum += g_deg[i];
    }
    sh[t] = sum;
    __syncthreads();
    for (int off = 128; off; off >>= 1) {
        if (t < off) sh[t] += sh[t + off];
        __syncthreads();
    }
    if (t == 0) g_chunksum[b] = sh[0];
}

__global__ void k_scanmid() {
    int run = 0;
    for (int c = 0; c < NCHUNK; c++) {
        g_chunkoff[c] = run;
        run += g_chunksum[c];
    }
    g_rowptr[N_NODES] = run;
}

__global__ void k_scanchunk() {
    __shared__ int s[1024];
    int b = blockIdx.x, t = threadIdx.x;
    int i = b * 1024 + t;
    int v = (i < N_NODES) ? g_deg[i] : 0;
    s[t] = v;
    __syncthreads();
    for (int off = 1; off < 1024; off <<= 1) {
        int add = (t >= off) ? s[t - off] : 0;
        __syncthreads();
        s[t] += add;
        __syncthreads();
    }
    if (i < N_NODES) {
        int ex = g_chunkoff[b] + s[t] - v;   // exclusive prefix
        g_rowptr[i] = ex;
        g_cursor[i] = ex;
    }
}

__global__ void k_scatter() {
    int e = blockIdx.x * blockDim.x + threadIdx.x;
    if (e >= N_EDGES) return;
    int dst = g_dst[e];
    int p = atomicAdd(&g_cursor[dst], 1);
    g_csr_src[p] = g_src[e];
    g_csr_dst[p] = dst;
    g_csr_eid[p] = e;
}

// logits in CSR order: 64 CSR slots/block, thread = (el = t>>2, h = t&3).
#define EA_STRIDE 68
__global__ void k_logits(const float* __restrict__ ea) {
    __shared__ float eas[64 * EA_STRIDE];
    __shared__ int ss[64], sd[64], se[64];
    int e0 = blockIdx.x * 64, t = threadIdx.x;
    if (t < 64) {
        ss[t] = g_csr_src[e0 + t];
        sd[t] = g_csr_dst[e0 + t];
        se[t] = g_csr_eid[e0 + t];
    }
    __syncthreads();
    // stage ea rows (gathered by eid): 4 threads per row, 16 floats each
    {
        int row = t >> 2, part = t & 3;
        const float4* src4 = (const float4*)(ea + (size_t)se[row] * 64 + part * 16);
        float* dstp = &eas[row * EA_STRIDE + part * 16];
#pragma unroll
        for (int k = 0; k < 4; k++) {
            float4 v = src4[k];
            dstp[k * 4 + 0] = v.x;
            dstp[k * 4 + 1] = v.y;
            dstp[k * 4 + 2] = v.z;
            dstp[k * 4 + 3] = v.w;
        }
    }
    __syncthreads();
    int el = t >> 2, h = t & 3;
    int dst = sd[el], src = ss[el];
    const float4* qp = (const float4*)(g_q + dst * 64 + h * 16);
    const float4* kp = (const float4*)(g_k + src * 64 + h * 16);
    float acc = 0.0f;
#pragma unroll
    for (int c = 0; c < 4; c++) {
        float4 qv = qp[c], kv = kp[c];
        acc += qv.x * kv.x + qv.y * kv.y + qv.z * kv.z + qv.w * kv.w;
    }
    const float4* pp = (const float4*)(g_p + dst * 256 + h * 64);
    const float4* er = (const float4*)&eas[el * EA_STRIDE];
#pragma unroll
    for (int j = 0; j < 16; j++) {
        float4 pv = pp[j];
        float4 ev = er[j];
        acc += ev.x * pv.x + ev.y * pv.y + ev.z * pv.z + ev.w * pv.w;
    }
    float logit = acc * 0.25f;   // 1/sqrt(16)
    g_att[e0 * 4 + t] = logit;   // coalesced
    atomicMax(&g_menc[dst * 4 + h], fenc(logit));
}

__global__ void k_exp() {
    int i = blockIdx.x * blockDim.x + threadIdx.x;
    if (i >= N_EDGES * HEADS) return;
    int e = i >> 2, h = i & 3;
    int dst = g_csr_dst[e];
    float m = fdec(g_menc[dst * 4 + h]);
    float ex = __expf(g_att[i] - m);
    g_att[i] = ex;               // unnormalized; k_prop applies g_dinv
    atomicAdd(&g_denom[dst * 4 + h], ex);
}

__global__ void k_dinv() {
    int i = blockIdx.x * blockDim.x + threadIdx.x;
    if (i < N_NODES * HEADS) g_dinv[i] = 1.0f / (g_denom[i] + 1e-16f);
}

// propagation: warp per node, pure gather, 4-way unrolled for MLP.
// Normalization folded in via g_dinv; iter==7 fuses relu + residual.
__global__ void k_prop(int iter, const float* __restrict__ x, float* __restrict__ out) {
    int gid = blockIdx.x * blockDim.x + threadIdx.x;
    int node = gid >> 5;
    if (node >= N_NODES) return;
    int lane = gid & 31;
    const float* zold = (iter == 0) ? g_v : ((iter & 1) ? g_zA : g_zB);
    float* znew = (iter & 1) ? g_zB : g_zA;
    int beg = g_rowptr[node], end = g_rowptr[node + 1];
    int h = lane >> 3;
    float inv = g_dinv[node * 4 + h];
    float ax0 = 0.f, ay0 = 0.f, ax1 = 0.f, ay1 = 0.f;
    float ax2 = 0.f, ay2 = 0.f, ax3 = 0.f, ay3 = 0.f;
    int i = beg;
    for (; i + 3 < end; i += 4) {
        int s0 = g_csr_src[i],     s1 = g_csr_src[i + 1];
        int s2 = g_csr_src[i + 2], s3 = g_csr_src[i + 3];
        float a0 = g_att[i * 4 + h];
        float a1 = g_att[(i + 1) * 4 + h];
        float a2 = g_att[(i + 2) * 4 + h];
        float a3 = g_att[(i + 3) * 4 + h];
        float2 z0 = *(const float2*)(zold + s0 * 64 + lane * 2);
        float2 z1 = *(const float2*)(zold + s1 * 64 + lane * 2);
        float2 z2 = *(const float2*)(zold + s2 * 64 + lane * 2);
        float2 z3 = *(const float2*)(zold + s3 * 64 + lane * 2);
        ax0 += a0 * z0.x; ay0 += a0 * z0.y;
        ax1 += a1 * z1.x; ay1 += a1 * z1.y;
        ax2 += a2 * z2.x; ay2 += a2 * z2.y;
        ax3 += a3 * z3.x; ay3 += a3 * z3.y;
    }
    for (; i < end; i++) {
        int s = g_csr_src[i];
        float a = g_att[i * 4 + h];
        float2 z = *(const float2*)(zold + s * 64 + lane * 2);
        ax0 += a * z.x; ay0 += a * z.y;
    }
    float ax = (ax0 + ax1) + (ax2 + ax3);
    float ay = (ay0 + ay1) + (ay2 + ay3);
    float2 vv = *(const float2*)(g_v + node * 64 + lane * 2);
    float ox = 0.1f * vv.x + 0.9f * (ax * inv);
    float oy = 0.1f * vv.y + 0.9f * (ay * inv);
    if (iter == 7) {
        float2 xv = *(const float2*)(x + node * 64 + lane * 2);
        float2 o;
        o.x = xv.x + fmaxf(ox, 0.0f);
        o.y = xv.y + fmaxf(oy, 0.0f);
        *(float2*)(out + node * 64 + lane * 2) = o;
    } else {
        float2 o; o.x = ox; o.y = oy;
        *(float2*)(znew + node * 64 + lane * 2) = o;
    }
}

// ---------------- launch ----------------
// Launch #4 is the ncu-profiled slot. This round k_p sits there (k_qkv was
// measured the last two rounds) -> walks the profiler through the pipeline.
extern "C" void kernel_launch(void* const* d_in, const int* in_sizes, int n_in,
                              void* d_out, int out_size) {
    const float*     x  = (const float*)d_in[0];
    const long long* ei = (const long long*)d_in[1];
    const float*     ea = (const float*)d_in[2];
    const float*     Wq = (const float*)d_in[3];
    const float*     Wk = (const float*)d_in[4];
    const float*     Wv = (const float*)d_in[5];
    const float*     We = (const float*)d_in[6];
    float* out = (float*)d_out;

    k_init<<<(N_NODES * HEADS + 255) / 256, 256>>>(ei);       // 1
    k_prep<<<(N_EDGES + 255) / 256, 256>>>(ei);               // 2
    k_qkv<<<(N_NODES + 63) / 64, 256>>>(x, Wq, Wk, Wv);       // 3
    k_p<<<N_NODES / 16, 256>>>(We);                           // 4  <- profiled
    k_chunksum<<<NCHUNK, 256>>>();                            // 5
    k_scanmid<<<1, 1>>>();                                    // 6
    k_scanchunk<<<NCHUNK, 1024>>>();                          // 7
    k_scatter<<<(N_EDGES + 255) / 256, 256>>>();              // 8
    k_logits<<<N_EDGES / 64, 256>>>(ea);                      // 9
    k_exp<<<(N_EDGES * HEADS + 255) / 256, 256>>>();          // 10
    k_dinv<<<(N_NODES * HEADS + 255) / 256, 256>>>();         // 11
    for (int it = 0; it < 8; it++)
        k_prop<<<(N_NODES * 32 + 255) / 256, 256>>>(it, x, out);  // 12-19
}

// round 13
// speedup vs baseline: 1.0682x; 1.0682x over previous
#include <cuda_runtime.h>
#include <cstdint>
#include <math_constants.h>

#define N_NODES 100000
#define N_EDGES 800000
#define DIM 64
#define HEADS 4
#define NCHUNK 98   // ceil(N_NODES/1024)

// ---------------- scratch (static __device__, no allocations) ----------------
__device__ float g_q[N_NODES * DIM];
__device__ float g_k[N_NODES * DIM];
__device__ float g_v[N_NODES * DIM];
__device__ float g_p[N_NODES * DIM * HEADS];     // [n][h*64+j]
__device__ float g_att[N_EDGES * HEADS];         // CSR order: logits -> exp(logit-m)
__device__ float g_dinv[N_NODES * HEADS];        // 1/(denom+eps)
__device__ int   g_src[N_EDGES];
__device__ int   g_dst[N_EDGES];
__device__ int   g_csr_src[N_EDGES];
__device__ int   g_csr_dst[N_EDGES];
__device__ int   g_csr_eid[N_EDGES];
__device__ int   g_deg[N_NODES];
__device__ int   g_rowptr[N_NODES + 1];
__device__ int   g_cursor[N_NODES];
__device__ int   g_chunksum[NCHUNK];
__device__ int   g_chunkoff[NCHUNK];
__device__ unsigned g_menc[N_NODES * HEADS];
__device__ float g_denom[N_NODES * HEADS];
__device__ float g_zA[N_NODES * DIM];
__device__ float g_zB[N_NODES * DIM];
__device__ int   g_is64;

// ordered-uint encoding of float for atomicMax
__device__ __forceinline__ unsigned fenc(float f) {
    unsigned u = __float_as_uint(f);
    return (u & 0x80000000u) ? ~u : (u | 0x80000000u);
}
__device__ __forceinline__ float fdec(unsigned u) {
    unsigned b = (u & 0x80000000u) ? (u & 0x7FFFFFFFu) : ~u;
    return __uint_as_float(b);
}

// packed f32x2 helpers (FFMA2 is only reachable via PTX fma.rn.f32x2)
__device__ __forceinline__ unsigned long long pk2(float a, float b) {
    unsigned long long r;
    asm("mov.b64 %0, {%1, %2};" : "=l"(r) : "f"(a), "f"(b));
    return r;
}
__device__ __forceinline__ unsigned long long ffma2(unsigned long long a,
                                                    unsigned long long b,
                                                    unsigned long long c) {
    unsigned long long d;
    asm("fma.rn.f32x2 %0, %1, %2, %3;" : "=l"(d) : "l"(a), "l"(b), "l"(c));
    return d;
}
__device__ __forceinline__ void upk2(unsigned long long v, float& lo, float& hi) {
    asm("mov.b64 {%0, %1}, %2;" : "=f"(lo), "=f"(hi) : "l"(v));
}

// ---------------- kernels ----------------

// fused: dtype detect (thread 0 of block 0) + zero-init of deg/menc/denom
__global__ void k_init(const long long* __restrict__ ei) {
    int i = blockIdx.x * blockDim.x + threadIdx.x;
    if (i == 0) {
        int ok = 1;
        for (int j = 0; j < 64; j++) {
            long long v = ei[j];
            if (v < 0 || v >= N_NODES) ok = 0;
        }
        g_is64 = ok;
    }
    if (i < N_NODES * HEADS) { g_menc[i] = 0u; g_denom[i] = 0.0f; }
    if (i < N_NODES) g_deg[i] = 0;
}

__global__ void k_prep(const long long* __restrict__ ei) {
    int i = blockIdx.x * blockDim.x + threadIdx.x;
    if (i >= N_EDGES) return;
    int s, d;
    if (g_is64) {
        s = (int)ei[i];
        d = (int)ei[N_EDGES + i];
    } else {
        const int* e32 = (const int*)ei;
        s = e32[i];
        d = e32[N_EDGES + i];
    }
    g_src[i] = s;
    g_dst[i] = d;
    atomicAdd(&g_deg[d], 1);
}

// q/k/v projections with packed f32x2 FMA (R9-measured config: 32 rows/block).
// xs[dim][row] transposed staging, stride 34 (8B-aligned row-pair loads,
// broadcast reads within warp).
__global__ void k_qkv(const float* __restrict__ x, const float* __restrict__ Wq,
                      const float* __restrict__ Wk, const float* __restrict__ Wv) {
    __shared__ float xs[64][34];
    int n0 = blockIdx.x * 32;
    int t = threadIdx.x;
    for (int kk = 0; kk < 8; kk++) {
        int L = kk * 256 + t;            // L = row*64 + dim
        xs[L & 63][L >> 6] = x[n0 * 64 + L];
    }
    __syncthreads();
    int col = t & 63, rg = t >> 6;
    unsigned long long aq[4], ak[4], av[4];
#pragma unroll
    for (int rp = 0; rp < 4; rp++) { aq[rp] = 0ull; ak[rp] = 0ull; av[rp] = 0ull; }
#pragma unroll 4
    for (int j = 0; j < 64; j++) {
        unsigned long long wq2 = pk2(Wq[j * 64 + col], Wq[j * 64 + col]);
        unsigned long long wk2 = pk2(Wk[j * 64 + col], Wk[j * 64 + col]);
        unsigned long long wv2 = pk2(Wv[j * 64 + col], Wv[j * 64 + col]);
        const unsigned long long* xr =
            (const unsigned long long*)&xs[j][rg * 8];   // 8B-aligned (stride 34)
#pragma unroll
        for (int rp = 0; rp < 4; rp++) {
            unsigned long long xv2 = xr[rp];             // rows {rg*8+2rp, +1}
            aq[rp] = ffma2(xv2, wq2, aq[rp]);
            ak[rp] = ffma2(xv2, wk2, ak[rp]);
            av[rp] = ffma2(xv2, wv2, av[rp]);
        }
    }
#pragma unroll
    for (int rp = 0; rp < 4; rp++) {
        int n = n0 + rg * 8 + rp * 2;
        float lo, hi;
        upk2(aq[rp], lo, hi);
        g_q[n * 64 + col] = lo; g_q[(n + 1) * 64 + col] = hi;
        upk2(ak[rp], lo, hi);
        g_k[n * 64 + col] = lo; g_k[(n + 1) * 64 + col] = hi;
        upk2(av[rp], lo, hi);
        g_v[n * 64 + col] = lo; g_v[(n + 1) * 64 + col] = hi;
    }
}

// p[n,h,j] = sum_d We[j, h*16+d] * q[n, h*16+d]   (16 nodes per block)
// LDS.128 reads: &qs[nl][h*16] is 64B-aligned -> 4 vector loads per node
// instead of 16 scalar loads (k_p was MIO-bound at L1=88.8%).
__global__ void k_p(const float* __restrict__ We) {
    __shared__ float qs[16][64];
    int n0 = blockIdx.x * 16, t = threadIdx.x;
    for (int k = 0; k < 4; k++) {
        int L = k * 256 + t;
        qs[L >> 6][L & 63] = g_q[n0 * 64 + L];
    }
    __syncthreads();
    int h = t >> 6, j = t & 63;
    const float4* wp = (const float4*)(We + j * 64 + h * 16);
    float4 w0 = wp[0], w1 = wp[1], w2 = wp[2], w3 = wp[3];
#pragma unroll 4
    for (int nl = 0; nl < 16; nl++) {
        const float4* qr4 = (const float4*)&qs[nl][h * 16];  // 64B-aligned
        float4 q0 = qr4[0], q1 = qr4[1], q2 = qr4[2], q3 = qr4[3];
        float acc = w0.x * q0.x + w0.y * q0.y + w0.z * q0.z + w0.w * q0.w
                  + w1.x * q1.x + w1.y * q1.y + w1.z * q1.z + w1.w * q1.w
                  + w2.x * q2.x + w2.y * q2.y + w2.z * q2.z + w2.w * q2.w
                  + w3.x * q3.x + w3.y * q3.y + w3.z * q3.z + w3.w * q3.w;
        g_p[(n0 + nl) * 256 + h * 64 + j] = acc;
    }
}

__global__ void k_chunksum() {
    __shared__ int sh[256];
    int b = blockIdx.x, t = threadIdx.x;
    int base = b * 1024;
    int sum = 0;
    for (int k = 0; k < 4; k++) {
        int i = base + k * 256 + t;
        if (i < N_NODES) sum += g_deg[i];
    }
    sh[t] = sum;
    __syncthreads();
    for (int off = 128; off; off >>= 1) {
        if (t < off) sh[t] += sh[t + off];
        __syncthreads();
    }
    if (t == 0) g_chunksum[b] = sh[0];
}

__global__ void k_scanmid() {
    int run = 0;
    for (int c = 0; c < NCHUNK; c++) {
        g_chunkoff[c] = run;
        run += g_chunksum[c];
    }
    g_rowptr[N_NODES] = run;
}

__global__ void k_scanchunk() {
    __shared__ int s[1024];
    int b = blockIdx.x, t = threadIdx.x;
    int i = b * 1024 + t;
    int v = (i < N_NODES) ? g_deg[i] : 0;
    s[t] = v;
    __syncthreads();
    for (int off = 1; off < 1024; off <<= 1) {
        int add = (t >= off) ? s[t - off] : 0;
        __syncthreads();
        s[t] += add;
        __syncthreads();
    }
    if (i < N_NODES) {
        int ex = g_chunkoff[b] + s[t] - v;   // exclusive prefix
        g_rowptr[i] = ex;
        g_cursor[i] = ex;
    }
}

__global__ void k_scatter() {
    int e = blockIdx.x * blockDim.x + threadIdx.x;
    if (e >= N_EDGES) return;
    int dst = g_dst[e];
    int p = atomicAdd(&g_cursor[dst], 1);
    g_csr_src[p] = g_src[e];
    g_csr_dst[p] = dst;
    g_csr_eid[p] = e;
}

// logits in CSR order: 64 CSR slots/block, thread = (el = t>>2, h = t&3).
#define EA_STRIDE 68
__global__ void k_logits(const float* __restrict__ ea) {
    __shared__ float eas[64 * EA_STRIDE];
    __shared__ int ss[64], sd[64], se[64];
    int e0 = blockIdx.x * 64, t = threadIdx.x;
    if (t < 64) {
        ss[t] = g_csr_src[e0 + t];
        sd[t] = g_csr_dst[e0 + t];
        se[t] = g_csr_eid[e0 + t];
    }
    __syncthreads();
    // stage ea rows (gathered by eid): 4 threads per row, 16 floats each
    {
        int row = t >> 2, part = t & 3;
        const float4* src4 = (const float4*)(ea + (size_t)se[row] * 64 + part * 16);
        float* dstp = &eas[row * EA_STRIDE + part * 16];
#pragma unroll
        for (int k = 0; k < 4; k++) {
            float4 v = src4[k];
            dstp[k * 4 + 0] = v.x;
            dstp[k * 4 + 1] = v.y;
            dstp[k * 4 + 2] = v.z;
            dstp[k * 4 + 3] = v.w;
        }
    }
    __syncthreads();
    int el = t >> 2, h = t & 3;
    int dst = sd[el], src = ss[el];
    const float4* qp = (const float4*)(g_q + dst * 64 + h * 16);
    const float4* kp = (const float4*)(g_k + src * 64 + h * 16);
    float acc = 0.0f;
#pragma unroll
    for (int c = 0; c < 4; c++) {
        float4 qv = qp[c], kv = kp[c];
        acc += qv.x * kv.x + qv.y * kv.y + qv.z * kv.z + qv.w * kv.w;
    }
    const float4* pp = (const float4*)(g_p + dst * 256 + h * 64);
    const float4* er = (const float4*)&eas[el * EA_STRIDE];
#pragma unroll
    for (int j = 0; j < 16; j++) {
        float4 pv = pp[j];
        float4 ev = er[j];
        acc += ev.x * pv.x + ev.y * pv.y + ev.z * pv.z + ev.w * pv.w;
    }
    float logit = acc * 0.25f;   // 1/sqrt(16)
    g_att[e0 * 4 + t] = logit;   // coalesced
    atomicMax(&g_menc[dst * 4 + h], fenc(logit));
}

__global__ void k_exp() {
    int i = blockIdx.x * blockDim.x + threadIdx.x;
    if (i >= N_EDGES * HEADS) return;
    int e = i >> 2, h = i & 3;
    int dst = g_csr_dst[e];
    float m = fdec(g_menc[dst * 4 + h]);
    float ex = __expf(g_att[i] - m);
    g_att[i] = ex;               // unnormalized; k_prop applies g_dinv
    atomicAdd(&g_denom[dst * 4 + h], ex);
}

__global__ void k_dinv() {
    int i = blockIdx.x * blockDim.x + threadIdx.x;
    if (i < N_NODES * HEADS) g_dinv[i] = 1.0f / (g_denom[i] + 1e-16f);
}

// propagation: warp per node, pure gather, 2-way unrolled (R9-measured config).
// Normalization folded in via g_dinv; iter==7 fuses relu + residual.
__global__ void k_prop(int iter, const float* __restrict__ x, float* __restrict__ out) {
    int gid = blockIdx.x * blockDim.x + threadIdx.x;
    int node = gid >> 5;
    if (node >= N_NODES) return;
    int lane = gid & 31;
    const float* zold = (iter == 0) ? g_v : ((iter & 1) ? g_zA : g_zB);
    float* znew = (iter & 1) ? g_zB : g_zA;
    int beg = g_rowptr[node], end = g_rowptr[node + 1];
    int h = lane >> 3;
    float inv = g_dinv[node * 4 + h];
    float ax0 = 0.0f, ay0 = 0.0f, ax1 = 0.0f, ay1 = 0.0f;
    int i = beg;
    for (; i + 1 < end; i += 2) {
        int s0 = g_csr_src[i], s1 = g_csr_src[i + 1];
        float a0 = g_att[i * 4 + h];
        float a1 = g_att[(i + 1) * 4 + h];
        float2 z0 = *(const float2*)(zold + s0 * 64 + lane * 2);
        float2 z1 = *(const float2*)(zold + s1 * 64 + lane * 2);
        ax0 += a0 * z0.x; ay0 += a0 * z0.y;
        ax1 += a1 * z1.x; ay1 += a1 * z1.y;
    }
    if (i < end) {
        int s = g_csr_src[i];
        float a = g_att[i * 4 + h];
        float2 z = *(const float2*)(zold + s * 64 + lane * 2);
        ax0 += a * z.x; ay0 += a * z.y;
    }
    float ax = ax0 + ax1, ay = ay0 + ay1;
    float2 vv = *(const float2*)(g_v + node * 64 + lane * 2);
    float ox = 0.1f * vv.x + 0.9f * (ax * inv);
    float oy = 0.1f * vv.y + 0.9f * (ay * inv);
    if (iter == 7) {
        float2 xv = *(const float2*)(x + node * 64 + lane * 2);
        float2 o;
        o.x = xv.x + fmaxf(ox, 0.0f);
        o.y = xv.y + fmaxf(oy, 0.0f);
        *(float2*)(out + node * 64 + lane * 2) = o;
    } else {
        float2 o; o.x = ox; o.y = oy;
        *(float2*)(znew + node * 64 + lane * 2) = o;
    }
}

// ---------------- launch ----------------
// Launch #4 is the ncu-profiled slot -> k_p sits there to verify the LDS.128
// prediction (expect ~20us, L1% way down, fma% up).
extern "C" void kernel_launch(void* const* d_in, const int* in_sizes, int n_in,
                              void* d_out, int out_size) {
    const float*     x  = (const float*)d_in[0];
    const long long* ei = (const long long*)d_in[1];
    const float*     ea = (const float*)d_in[2];
    const float*     Wq = (const float*)d_in[3];
    const float*     Wk = (const float*)d_in[4];
    const float*     Wv = (const float*)d_in[5];
    const float*     We = (const float*)d_in[6];
    float* out = (float*)d_out;

    k_init<<<(N_NODES * HEADS + 255) / 256, 256>>>(ei);       // 1
    k_prep<<<(N_EDGES + 255) / 256, 256>>>(ei);               // 2
    k_qkv<<<N_NODES / 32, 256>>>(x, Wq, Wk, Wv);              // 3
    k_p<<<N_NODES / 16, 256>>>(We);                           // 4  <- profiled
    k_chunksum<<<NCHUNK, 256>>>();                            // 5
    k_scanmid<<<1, 1>>>();                                    // 6
    k_scanchunk<<<NCHUNK, 1024>>>();                          // 7
    k_scatter<<<(N_EDGES + 255) / 256, 256>>>();              // 8
    k_logits<<<N_EDGES / 64, 256>>>(ea);                      // 9
    k_exp<<<(N_EDGES * HEADS + 255) / 256, 256>>>();          // 10
    k_dinv<<<(N_NODES * HEADS + 255) / 256, 256>>>();         // 11
    for (int it = 0; it < 8; it++)
        k_prop<<<(N_NODES * 32 + 255) / 256, 256>>>(it, x, out);  // 12-19
}